// round 1
// baseline (speedup 1.0000x reference)
#include <cuda_runtime.h>
#include <math.h>

#define NF 26
#define ND 16
#define H1 256
#define H2 128
#define ROWS 32
#define K1 (NF*ND)   // 416
#define EPSF 1e-5f

__global__ __launch_bounds__(256, 2)
void deepfm_fused(const int* __restrict__ X, const float* __restrict__ emb1,
                  const float* __restrict__ emb2,
                  const float* __restrict__ W1, const float* __restrict__ b1,
                  const float* __restrict__ g1, const float* __restrict__ be1,
                  const float* __restrict__ m1, const float* __restrict__ v1,
                  const float* __restrict__ W2, const float* __restrict__ b2,
                  const float* __restrict__ g2, const float* __restrict__ be2,
                  const float* __restrict__ m2, const float* __restrict__ v2,
                  const float* __restrict__ W3, const float* __restrict__ b3,
                  float* __restrict__ out, int B, int V)
{
    extern __shared__ float sm[];
    float* e2sT    = sm;                 // [K1][ROWS] = 13312 floats; later reused as h1sT [256][33]
    float* fm_s    = sm + K1*ROWS;       // [ROWS]
    float* logit_s = fm_s + ROWS;        // [ROWS]

    const int tid = threadIdx.x;
    const int b0  = blockIdx.x * ROWS;

    if (tid < ROWS) { fm_s[tid] = 0.f; logit_s[tid] = 0.f; }
    __syncthreads();

    // ---- Phase 1: gather e2 (transposed into smem) + first-order FM ----
    for (int p = tid; p < ROWS*NF; p += 256) {
        int r = p & (ROWS-1);
        int f = p >> 5;            // 0..25
        int row = b0 + r;
        int idx = X[row*NF + f];
        atomicAdd(&fm_s[r], emb1[(long)f*V + idx]);
        const float4* src = (const float4*)(emb2 + ((long)f*V + idx)*ND);
        #pragma unroll
        for (int q = 0; q < 4; q++) {
            float4 v = src[q];
            e2sT[(f*ND + 4*q + 0)*ROWS + r] = v.x;
            e2sT[(f*ND + 4*q + 1)*ROWS + r] = v.y;
            e2sT[(f*ND + 4*q + 2)*ROWS + r] = v.z;
            e2sT[(f*ND + 4*q + 3)*ROWS + r] = v.w;
        }
    }
    __syncthreads();

    // ---- Phase 2: second-order FM: 0.5*((sum_f e)^2 - sum_f e^2), summed over d ----
    {
        int p = tid;               // 512 (r,d) pairs, 2 per thread
        #pragma unroll
        for (int it = 0; it < 2; it++) {
            int r = p & (ROWS-1);
            int d = p >> 5;        // 0..15
            float s = 0.f, sq = 0.f;
            #pragma unroll
            for (int f = 0; f < NF; f++) {
                float v = e2sT[(f*ND + d)*ROWS + r];
                s += v; sq += v*v;
            }
            atomicAdd(&fm_s[r], 0.5f*(s*s - sq));
            p += 256;
        }
    }

    // ---- Phase 3: GEMM1 (416 x 256), thread owns column j = tid, 32 row accumulators ----
    float acc[ROWS];
    #pragma unroll
    for (int r = 0; r < ROWS; r++) acc[r] = 0.f;
    const int j = tid;
    #pragma unroll 2
    for (int k = 0; k < K1; k++) {
        float w = W1[k*H1 + j];                          // coalesced, L2-resident
        const float4* e4 = (const float4*)(e2sT + k*ROWS); // warp-uniform broadcast
        #pragma unroll
        for (int q = 0; q < 8; q++) {
            float4 e = e4[q];
            acc[4*q+0] += e.x*w;
            acc[4*q+1] += e.y*w;
            acc[4*q+2] += e.z*w;
            acc[4*q+3] += e.w*w;
        }
    }
    __syncthreads();   // everyone done reading e2sT

    // ---- BN1 (folded) + ReLU, write h1 transposed with stride 33 (conflict-free) ----
    {
        float S  = g1[j]*rsqrtf(v1[j]+EPSF);
        float Bi = be1[j] + (b1[j]-m1[j])*S;
        #pragma unroll
        for (int r = 0; r < ROWS; r++) {
            float h = fmaxf(acc[r]*S + Bi, 0.f);
            e2sT[j*(ROWS+1) + r] = h;                    // h1sT[k=j][r], max idx 8446 < 13312
        }
    }
    __syncthreads();

    // ---- Phase 4: GEMM2 (256 x 128), thread owns (j2, 16 rows) ----
    float acc2[16];
    #pragma unroll
    for (int rr = 0; rr < 16; rr++) acc2[rr] = 0.f;
    const int j2 = tid & (H2-1);
    const int rb = (tid >> 7) * 16;
    #pragma unroll 2
    for (int k = 0; k < H1; k++) {
        float w = W2[k*H2 + j2];
        const float* hrow = e2sT + k*(ROWS+1) + rb;      // warp-uniform broadcast
        #pragma unroll
        for (int rr = 0; rr < 16; rr++)
            acc2[rr] += hrow[rr]*w;
    }

    // ---- BN2 + ReLU + W3 dot via warp-shuffle reduce ----
    {
        float S2 = g2[j2]*rsqrtf(v2[j2]+EPSF);
        float B2 = be2[j2] + (b2[j2]-m2[j2])*S2;
        float w3 = W3[j2];
        #pragma unroll
        for (int rr = 0; rr < 16; rr++) {
            float h = fmaxf(acc2[rr]*S2 + B2, 0.f);
            float c = h*w3;
            #pragma unroll
            for (int o = 16; o > 0; o >>= 1)
                c += __shfl_xor_sync(0xffffffffu, c, o);
            if ((tid & 31) == 0) atomicAdd(&logit_s[rb+rr], c);
        }
    }
    __syncthreads();

    // ---- Epilogue: logits + FM + bias, sigmoid ----
    if (tid < ROWS) {
        float x = logit_s[tid] + fm_s[tid] + b3[0];
        out[b0+tid] = 1.f/(1.f+expf(-x));
    }
}

extern "C" void kernel_launch(void* const* d_in, const int* in_sizes, int n_in,
                              void* d_out, int out_size)
{
    const int*   X    = (const int*)  d_in[0];
    const float* emb1 = (const float*)d_in[1];
    const float* emb2 = (const float*)d_in[2];
    const float* W1   = (const float*)d_in[3];
    const float* b1   = (const float*)d_in[4];
    const float* g1   = (const float*)d_in[5];
    const float* be1  = (const float*)d_in[6];
    const float* m1   = (const float*)d_in[7];
    const float* v1   = (const float*)d_in[8];
    const float* W2   = (const float*)d_in[9];
    const float* b2   = (const float*)d_in[10];
    const float* g2   = (const float*)d_in[11];
    const float* be2  = (const float*)d_in[12];
    const float* m2   = (const float*)d_in[13];
    const float* v2   = (const float*)d_in[14];
    const float* W3   = (const float*)d_in[15];
    const float* b3   = (const float*)d_in[16];
    float* out = (float*)d_out;

    int B = in_sizes[0] / NF;
    int V = in_sizes[1] / NF;

    int smem = (K1*ROWS + 2*ROWS) * (int)sizeof(float);   // 53504 B
    cudaFuncSetAttribute(deepfm_fused, cudaFuncAttributeMaxDynamicSharedMemorySize, smem);
    deepfm_fused<<<B/ROWS, 256, smem>>>(X, emb1, emb2, W1, b1, g1, be1, m1, v1,
                                        W2, b2, g2, be2, m2, v2, W3, b3,
                                        out, B, V);
}

// round 4
// speedup vs baseline: 1.4134x; 1.4134x over previous
#include <cuda_runtime.h>
#include <math.h>
#include <stdint.h>

#define NF 26
#define ND 16
#define H1 256
#define H2 128
#define ROWS 32
#define K1 (NF*ND)     // 416
#define EPSF 1e-5f

// smem float offsets
#define OFF_FM     (K1*ROWS)          // 13312
#define OFF_LOGIT  (OFF_FM + 32)
#define OFF_S1     (OFF_LOGIT + 32)
#define OFF_B1     (OFF_S1 + 256)
#define OFF_S2     (OFF_B1 + 256)
#define OFF_B2     (OFF_S2 + 128)
#define OFF_W3     (OFF_B2 + 128)
#define SMEM_FLOATS (OFF_W3 + 128)    // 14272 -> 57088 B
#define H1_STRIDE  36                 // floats; 144B rows, 16B aligned

__device__ __forceinline__ uint32_t smem_u32(const void* p){
    uint32_t a;
    asm("{ .reg .u64 t; cvta.to.shared.u64 t, %1; cvt.u32.u64 %0, t; }" : "=r"(a) : "l"(p));
    return a;
}
__device__ __forceinline__ unsigned long long packf2(float x){
    unsigned long long r;
    asm("mov.b64 %0, {%1, %1};" : "=l"(r) : "f"(x));
    return r;
}
__device__ __forceinline__ unsigned long long pack2(float lo, float hi){
    unsigned long long r;
    asm("mov.b64 %0, {%1, %2};" : "=l"(r) : "f"(lo), "f"(hi));
    return r;
}
__device__ __forceinline__ void unpack2(unsigned long long a, float& lo, float& hi){
    asm("mov.b64 {%0, %1}, %2;" : "=f"(lo), "=f"(hi) : "l"(a));
}
__device__ __forceinline__ void fma2(unsigned long long& a, unsigned long long e, unsigned long long w){
    asm("fma.rn.f32x2 %0, %1, %2, %0;" : "+l"(a) : "l"(e), "l"(w));
}
__device__ __forceinline__ void lds2x64(unsigned long long& a, unsigned long long& b, uint32_t addr){
    asm volatile("ld.shared.v2.u64 {%0, %1}, [%2];" : "=l"(a), "=l"(b) : "r"(addr));
}
__device__ __forceinline__ void sts64(uint32_t addr, unsigned long long v){
    asm volatile("st.shared.u64 [%0], %1;" :: "r"(addr), "l"(v));
}

__global__ __launch_bounds__(256, 2)
void deepfm_v2(const int* __restrict__ X, const float* __restrict__ emb1,
               const float* __restrict__ emb2,
               const float* __restrict__ W1, const float* __restrict__ b1,
               const float* __restrict__ g1, const float* __restrict__ be1,
               const float* __restrict__ m1, const float* __restrict__ v1,
               const float* __restrict__ W2, const float* __restrict__ b2,
               const float* __restrict__ g2, const float* __restrict__ be2,
               const float* __restrict__ m2, const float* __restrict__ v2,
               const float* __restrict__ W3, const float* __restrict__ b3,
               float* __restrict__ out, int Btot, int V)
{
    extern __shared__ float sm[];
    float* e2sT    = sm;                  // [K1][32], reused later as h1s [256][36]
    float* fm_s    = sm + OFF_FM;
    float* logit_s = sm + OFF_LOGIT;
    float* S1f     = sm + OFF_S1;
    float* B1f     = sm + OFF_B1;
    float* S2f     = sm + OFF_S2;
    float* B2f     = sm + OFF_B2;
    float* W3s     = sm + OFF_W3;

    const int tid = threadIdx.x;
    const int b0  = blockIdx.x * ROWS;
    const uint32_t smbase = smem_u32(sm);

    if (tid < 32) { fm_s[tid] = 0.f; logit_s[tid] = 0.f; }
    {   // folded BN params (all 256 threads hit layer1; low half also layer2 + W3)
        float s = g1[tid] * rsqrtf(v1[tid] + EPSF);
        S1f[tid] = s; B1f[tid] = be1[tid] + (b1[tid] - m1[tid]) * s;
        if (tid < 128) {
            float s2 = g2[tid] * rsqrtf(v2[tid] + EPSF);
            S2f[tid] = s2; B2f[tid] = be2[tid] + (b2[tid] - m2[tid]) * s2;
            W3s[tid] = W3[tid];
        }
    }
    __syncthreads();

    // ---- Phase 1: gather e2 transposed into smem + first-order FM ----
    for (int p = tid; p < ROWS*NF; p += 256) {
        int r = p & (ROWS-1);
        int f = p >> 5;                 // 0..25
        int idx = X[(size_t)(b0 + r) * NF + f];
        atomicAdd(&fm_s[r], emb1[(size_t)f * V + idx]);
        const float4* src = (const float4*)(emb2 + ((size_t)f * V + idx) * ND);
        #pragma unroll
        for (int q = 0; q < 4; q++) {
            float4 v = src[q];
            e2sT[(f*ND + 4*q + 0)*ROWS + r] = v.x;
            e2sT[(f*ND + 4*q + 1)*ROWS + r] = v.y;
            e2sT[(f*ND + 4*q + 2)*ROWS + r] = v.z;
            e2sT[(f*ND + 4*q + 3)*ROWS + r] = v.w;
        }
    }
    __syncthreads();

    // ---- Phase 2: second-order FM ----
    {
        int p = tid;
        #pragma unroll
        for (int it = 0; it < 2; it++) {
            int r = p & (ROWS-1);
            int d = p >> 5;             // 0..15
            float s = 0.f, sq = 0.f;
            #pragma unroll
            for (int f = 0; f < NF; f++) {
                float v = e2sT[(f*ND + d)*ROWS + r];
                s += v; sq += v*v;
            }
            atomicAdd(&fm_s[r], 0.5f*(s*s - sq));
            p += 256;
        }
    }

    // ---- Phase 3: GEMM1 (K=416 -> 256 cols), thread = 4 cols x 8 rows, f32x2 ----
    const int jq = tid >> 2;            // 0..63 -> cols 4jq..4jq+3
    const int rg = tid & 3;             // 0..3  -> rows 8rg..8rg+7
    unsigned long long acc[16];         // [c][p] : cols c<4, row-pairs p<4
    #pragma unroll
    for (int i = 0; i < 16; i++) acc[i] = 0ull;

    {
        const float4* wp = (const float4*)(W1 + 4*jq);   // stride 64 float4 per k
        uint32_t ea = smbase + (uint32_t)rg * 32u;       // + k*128 per k
        #pragma unroll 4
        for (int k = 0; k < K1; k++) {
            float4 wv = wp[(size_t)k * (H1/4)];
            unsigned long long e0, e1, e2, e3;
            lds2x64(e0, e1, ea);
            lds2x64(e2, e3, ea + 16u);
            ea += 128u;
            unsigned long long w0 = packf2(wv.x), w1 = packf2(wv.y),
                               w2 = packf2(wv.z), w3p = packf2(wv.w);
            fma2(acc[0],  e0, w0); fma2(acc[1],  e1, w0); fma2(acc[2],  e2, w0); fma2(acc[3],  e3, w0);
            fma2(acc[4],  e0, w1); fma2(acc[5],  e1, w1); fma2(acc[6],  e2, w1); fma2(acc[7],  e3, w1);
            fma2(acc[8],  e0, w2); fma2(acc[9],  e1, w2); fma2(acc[10], e2, w2); fma2(acc[11], e3, w2);
            fma2(acc[12], e0, w3p); fma2(acc[13], e1, w3p); fma2(acc[14], e2, w3p); fma2(acc[15], e3, w3p);
        }
    }
    __syncthreads();    // all reads of e2sT done (phase2 + GEMM1) before overwrite

    // ---- BN1 + ReLU -> h1s [256][36] (reuses e2sT region) ----
    {
        #pragma unroll
        for (int cc = 0; cc < 4; cc++) {
            int col = 4*jq + cc;
            float S = S1f[col], Bv = B1f[col];
            uint32_t ha = smbase + ((uint32_t)col * H1_STRIDE + (uint32_t)rg * 8u) * 4u;
            #pragma unroll
            for (int p = 0; p < 4; p++) {
                float lo, hi; unpack2(acc[cc*4 + p], lo, hi);
                lo = fmaxf(lo*S + Bv, 0.f);
                hi = fmaxf(hi*S + Bv, 0.f);
                sts64(ha + (uint32_t)p * 8u, pack2(lo, hi));
            }
        }
    }
    __syncthreads();

    // ---- Phase 4: GEMM2 (K=256 -> 128 cols), thread = 4 cols x 4 rows ----
    const int jq2 = tid >> 3;           // 0..31 -> cols 4jq2..4jq2+3
    const int rg2 = tid & 7;            // 0..7  -> rows 4rg2..4rg2+3
    unsigned long long acc2[8];         // [c][p] c<4, p<2
    #pragma unroll
    for (int i = 0; i < 8; i++) acc2[i] = 0ull;
    {
        const float4* wp2 = (const float4*)(W2 + 4*jq2);
        uint32_t ha = smbase + (uint32_t)rg2 * 16u;      // + k*144 per k
        #pragma unroll 4
        for (int k = 0; k < H1; k++) {
            float4 wv = wp2[(size_t)k * (H2/4)];
            unsigned long long e0, e1;
            lds2x64(e0, e1, ha);
            ha += (uint32_t)(H1_STRIDE*4);
            unsigned long long w0 = packf2(wv.x), w1 = packf2(wv.y),
                               w2 = packf2(wv.z), w3p = packf2(wv.w);
            fma2(acc2[0], e0, w0); fma2(acc2[1], e1, w0);
            fma2(acc2[2], e0, w1); fma2(acc2[3], e1, w1);
            fma2(acc2[4], e0, w2); fma2(acc2[5], e1, w2);
            fma2(acc2[6], e0, w3p); fma2(acc2[7], e1, w3p);
        }
    }

    // ---- BN2 + ReLU + W3 partial dots -> smem logits ----
    {
        float contrib[4] = {0.f, 0.f, 0.f, 0.f};
        #pragma unroll
        for (int cc = 0; cc < 4; cc++) {
            int col = 4*jq2 + cc;
            float S = S2f[col], Bv = B2f[col], w3 = W3s[col];
            #pragma unroll
            for (int p = 0; p < 2; p++) {
                float lo, hi; unpack2(acc2[cc*2 + p], lo, hi);
                contrib[2*p]   += fmaxf(lo*S + Bv, 0.f) * w3;
                contrib[2*p+1] += fmaxf(hi*S + Bv, 0.f) * w3;
            }
        }
        #pragma unroll
        for (int rr = 0; rr < 4; rr++)
            atomicAdd(&logit_s[4*rg2 + rr], contrib[rr]);
    }
    __syncthreads();

    // ---- Epilogue ----
    if (tid < ROWS) {
        float x = logit_s[tid] + fm_s[tid] + b3[0];
        out[b0 + tid] = 1.f / (1.f + expf(-x));
    }
}

extern "C" void kernel_launch(void* const* d_in, const int* in_sizes, int n_in,
                              void* d_out, int out_size)
{
    const int*   X    = (const int*)  d_in[0];
    const float* emb1 = (const float*)d_in[1];
    const float* emb2 = (const float*)d_in[2];
    const float* W1   = (const float*)d_in[3];
    const float* b1   = (const float*)d_in[4];
    const float* g1   = (const float*)d_in[5];
    const float* be1  = (const float*)d_in[6];
    const float* m1   = (const float*)d_in[7];
    const float* v1   = (const float*)d_in[8];
    const float* W2   = (const float*)d_in[9];
    const float* b2   = (const float*)d_in[10];
    const float* g2   = (const float*)d_in[11];
    const float* be2  = (const float*)d_in[12];
    const float* m2   = (const float*)d_in[13];
    const float* v2   = (const float*)d_in[14];
    const float* W3   = (const float*)d_in[15];
    const float* b3   = (const float*)d_in[16];
    float* out = (float*)d_out;

    int B = in_sizes[0] / NF;
    int V = in_sizes[1] / NF;

    int smem = SMEM_FLOATS * (int)sizeof(float);   // 57088 B
    cudaFuncSetAttribute(deepfm_v2, cudaFuncAttributeMaxDynamicSharedMemorySize, smem);
    deepfm_v2<<<B/ROWS, 256, smem>>>(X, emb1, emb2, W1, b1, g1, be1, m1, v1,
                                     W2, b2, g2, be2, m2, v2, W3, b3,
                                     out, B, V);
}